// round 1
// baseline (speedup 1.0000x reference)
#include <cuda_runtime.h>

#define T_STEPS 800
#define UNITS   1024
#define BATCH   32
#define NFEAT   161
#define GRID    128
#define TPB     256
#define CK      16          // k-chunks
#define CN      8           // column tiles
#define KC      64          // UNITS / CK
#define NC      128         // UNITS / CN
#define CLIPV   20.0f

// Persistent scratch (device globals: allocation-free per harness rules)
__device__ float    g_xw[T_STEPS * UNITS * BATCH];   // [t][u][b]  ~100MB
__device__ float    g_h[2 * UNITS * BATCH];          // [dir][u][b]
__device__ float    g_part[CK * 2 * UNITS * BATCH];  // [kc][dir][u][b] 4MB
__device__ unsigned g_bar;

typedef unsigned long long ull;

__device__ __forceinline__ void fma2(ull& d, ull a, ull b) {
    asm("fma.rn.f32x2 %0, %1, %2, %0;" : "+l"(d) : "l"(a), "l"(b));
}
__device__ __forceinline__ ull pack2(float v) {
    ull r; asm("mov.b64 %0, {%1, %1};" : "=l"(r) : "f"(v)); return r;
}
__device__ __forceinline__ float2 unpack2(ull v) {
    float2 r; asm("mov.b64 {%0, %1}, %2;" : "=f"(r.x), "=f"(r.y) : "l"(v)); return r;
}

// ---------------------------------------------------------------------------
// Init: reset barrier counter + zero h (must run every launch: globals persist)
// ---------------------------------------------------------------------------
__global__ void init_kernel() {
    int i = blockIdx.x * blockDim.x + threadIdx.x;
    if (i < 2 * UNITS * BATCH) g_h[i] = 0.0f;
    if (i == 0) g_bar = 0u;
}

// ---------------------------------------------------------------------------
// Kernel 1: xw[t][u][b] = sum_f inputs[b][t][f] * W[f][u] + bias[u]
// grid (8 u-tiles, 800 t), 256 threads. Per-thread 4b x 4u, f32x2 FMAs.
// ---------------------------------------------------------------------------
__global__ void __launch_bounds__(TPB) xw_kernel(const float* __restrict__ inp,
                                                 const float* __restrict__ W,
                                                 const float* __restrict__ bias) {
    __shared__ __align__(16) float in_s[NFEAT * 36];  // padded rows (16B-aligned, low-conflict)
    const int t   = blockIdx.y;
    const int u0  = blockIdx.x * NC;
    const int tid = threadIdx.x;
    const int bq  = tid & 7;    // 8 groups of 4 batches
    const int cq  = tid >> 3;   // 32 groups of 4 units

    // stage inputs[b][t][:] transposed to in_s[f][b]
    for (int idx = tid; idx < BATCH * NFEAT; idx += TPB) {
        int b = idx / NFEAT;
        int f = idx - b * NFEAT;
        in_s[f * 36 + b] = inp[(b * T_STEPS + t) * NFEAT + f];
    }
    __syncthreads();

    ull acc[4][2];
    #pragma unroll
    for (int i = 0; i < 4; i++) { acc[i][0] = 0ull; acc[i][1] = 0ull; }

    const float4* Wp = reinterpret_cast<const float4*>(W) + (u0 >> 2) + cq;
    #pragma unroll 1
    for (int f = 0; f < NFEAT; f++) {
        ulonglong2 ip = *reinterpret_cast<const ulonglong2*>(&in_s[f * 36 + bq * 4]);
        float4 w4 = __ldg(Wp + f * (UNITS / 4));
        ull w0 = pack2(w4.x), w1 = pack2(w4.y), w2 = pack2(w4.z), w3 = pack2(w4.w);
        fma2(acc[0][0], ip.x, w0); fma2(acc[0][1], ip.y, w0);
        fma2(acc[1][0], ip.x, w1); fma2(acc[1][1], ip.y, w1);
        fma2(acc[2][0], ip.x, w2); fma2(acc[2][1], ip.y, w2);
        fma2(acc[3][0], ip.x, w3); fma2(acc[3][1], ip.y, w3);
    }
    #pragma unroll
    for (int i = 0; i < 4; i++) {
        int u = u0 + cq * 4 + i;
        float bu = __ldg(bias + u);
        float2 a0 = unpack2(acc[i][0]);
        float2 a1 = unpack2(acc[i][1]);
        float4 v = make_float4(a0.x + bu, a0.y + bu, a1.x + bu, a1.y + bu);
        *reinterpret_cast<float4*>(&g_xw[(t * UNITS + u) * BATCH + bq * 4]) = v;
    }
}

// ---------------------------------------------------------------------------
// Grid-wide barrier: monotonic counter, release-red arrive + acquire-ld spin.
// Safe: GRID=128 CTAs <= 148 SMs, 1 CTA/SM guaranteed resident.
// ---------------------------------------------------------------------------
__device__ __forceinline__ void grid_sync(unsigned target) {
    __syncthreads();
    if (threadIdx.x == 0) {
        unsigned* bar = &g_bar;
        asm volatile("red.release.gpu.global.add.u32 [%0], %1;"
                     :: "l"(bar), "r"(1u) : "memory");
        unsigned v;
        do {
            asm volatile("ld.acquire.gpu.global.u32 %0, [%1];"
                         : "=r"(v) : "l"(bar) : "memory");
        } while (v < target);
    }
    __syncthreads();
}

// ---------------------------------------------------------------------------
// Kernel 2: persistent bidirectional RNN scan.
// CTA (kc, nc): partial = h[dir][k-chunk] @ U[k-chunk][col-tile], both dirs.
// Phase 2 (all CTAs): reduce CK partials + x_t, relu, clip -> new h.
// ---------------------------------------------------------------------------
__global__ void __launch_bounds__(TPB, 1) rnn_kernel(const float* __restrict__ Uw,
                                                     float* __restrict__ out) {
    __shared__ __align__(16) float U_s[KC * NC];         // 32 KB, resident all rounds
    __shared__ __align__(16) float h_s[2 * KC * BATCH];  // 16 KB, restaged per round

    const int tid = threadIdx.x;
    const int bq  = tid & 7;          // batch group (4 batches)
    const int cq  = tid >> 3;         // column group (4 columns)
    const int bid = blockIdx.x;
    const int nc  = bid & (CN - 1);
    const int kc  = bid >> 3;
    const int c0  = nc * NC;
    const int k0  = kc * KC;

    // load U slice once
    for (int idx = tid; idx < KC * NC / 4; idx += TPB) {
        int k  = idx >> 5;            // NC/4 = 32 float4 per row
        int c4 = idx & 31;
        reinterpret_cast<float4*>(U_s)[idx] =
            __ldg(reinterpret_cast<const float4*>(Uw + (k0 + k) * UNITS + c0) + c4);
    }

    unsigned bseq = 0;

    for (int t = 0; t < T_STEPS; t++) {
        // ---- Phase 1: stage h chunk (both dirs), .cg (cross-SM data) ----
        #pragma unroll
        for (int j = 0; j < 4; j++) {                 // 1024 float4 total
            int idx  = tid + j * TPB;
            int dir  = idx >> 9;
            int rem  = idx & 511;                     // k*8 + b4
            float4 v = __ldcg(reinterpret_cast<const float4*>(g_h)
                              + dir * (UNITS * BATCH / 4) + k0 * (BATCH / 4) + rem);
            reinterpret_cast<float4*>(h_s)[idx] = v;
        }
        __syncthreads();

        ull acc[2][4][2];
        #pragma unroll
        for (int d = 0; d < 2; d++)
            #pragma unroll
            for (int i = 0; i < 4; i++) { acc[d][i][0] = 0ull; acc[d][i][1] = 0ull; }

        #pragma unroll 2
        for (int k = 0; k < KC; k++) {
            ulonglong2 hp0 = *reinterpret_cast<const ulonglong2*>(&h_s[k * BATCH + bq * 4]);
            ulonglong2 hp1 = *reinterpret_cast<const ulonglong2*>(&h_s[(KC + k) * BATCH + bq * 4]);
            float4 u4 = *reinterpret_cast<const float4*>(&U_s[k * NC + cq * 4]);
            ull w0 = pack2(u4.x), w1 = pack2(u4.y), w2 = pack2(u4.z), w3 = pack2(u4.w);
            fma2(acc[0][0][0], hp0.x, w0); fma2(acc[0][0][1], hp0.y, w0);
            fma2(acc[0][1][0], hp0.x, w1); fma2(acc[0][1][1], hp0.y, w1);
            fma2(acc[0][2][0], hp0.x, w2); fma2(acc[0][2][1], hp0.y, w2);
            fma2(acc[0][3][0], hp0.x, w3); fma2(acc[0][3][1], hp0.y, w3);
            fma2(acc[1][0][0], hp1.x, w0); fma2(acc[1][0][1], hp1.y, w0);
            fma2(acc[1][1][0], hp1.x, w1); fma2(acc[1][1][1], hp1.y, w1);
            fma2(acc[1][2][0], hp1.x, w2); fma2(acc[1][2][1], hp1.y, w2);
            fma2(acc[1][3][0], hp1.x, w3); fma2(acc[1][3][1], hp1.y, w3);
        }

        // partial stores: float4 over 4 adjacent batches -> fully coalesced
        #pragma unroll
        for (int d = 0; d < 2; d++)
            #pragma unroll
            for (int i = 0; i < 4; i++) {
                float2 a0 = unpack2(acc[d][i][0]);
                float2 a1 = unpack2(acc[d][i][1]);
                float4 v  = make_float4(a0.x, a0.y, a1.x, a1.y);
                __stcg(reinterpret_cast<float4*>(
                           &g_part[(((kc * 2 + d) * UNITS) + (c0 + cq * 4 + i)) * BATCH + bq * 4]),
                       v);
            }

        bseq++; grid_sync(bseq * GRID);

        // ---- Phase 2: reduce partials, add x_t, relu+clip, write h ----
        if (tid < 128) {
            int q   = bid * 128 + tid;     // 16384 float4 = 2 dirs * 1024 u * 8 b4
            int dir = q >> 13;
            int rem = q & 8191;            // u*8 + b4
            float4 s = make_float4(0.f, 0.f, 0.f, 0.f);
            const float4* pb = reinterpret_cast<const float4*>(g_part);
            #pragma unroll
            for (int j = 0; j < CK; j++) {
                float4 p = __ldcg(pb + (j * 2 + dir) * (UNITS * BATCH / 4) + rem);
                s.x += p.x; s.y += p.y; s.z += p.z; s.w += p.w;
            }
            int tx   = dir ? (T_STEPS - 1 - t) : t;
            float4 x = __ldg(reinterpret_cast<const float4*>(g_xw)
                             + tx * (UNITS * BATCH / 4) + rem);
            float4 hn;
            hn.x = fminf(fmaxf(x.x + s.x, 0.f), CLIPV);
            hn.y = fminf(fmaxf(x.y + s.y, 0.f), CLIPV);
            hn.z = fminf(fmaxf(x.z + s.z, 0.f), CLIPV);
            hn.w = fminf(fmaxf(x.w + s.w, 0.f), CLIPV);
            __stcg(reinterpret_cast<float4*>(g_h) + dir * (UNITS * BATCH / 4) + rem, hn);
        }

        bseq++; grid_sync(bseq * GRID);
    }

    // epilogue: out[b][u] = h_fwd[u][b] + h_bwd[u][b]   (32768 = GRID*TPB)
    {
        int o = bid * TPB + tid;
        int b = o >> 10;
        int u = o & 1023;
        float v = __ldcg(&g_h[u * BATCH + b]) +
                  __ldcg(&g_h[UNITS * BATCH + u * BATCH + b]);
        out[o] = v;
    }
}

// ---------------------------------------------------------------------------
extern "C" void kernel_launch(void* const* d_in, const int* in_sizes, int n_in,
                              void* d_out, int out_size) {
    const float* inp  = (const float*)d_in[0];  // [32, 800, 161]
    const float* W    = (const float*)d_in[1];  // [161, 1024]
    const float* Uw   = (const float*)d_in[2];  // [1024, 1024]
    const float* bias = (const float*)d_in[3];  // [1024]
    float* out        = (float*)d_out;          // [32, 1024]

    init_kernel<<<(2 * UNITS * BATCH + TPB - 1) / TPB, TPB>>>();
    xw_kernel<<<dim3(CN, T_STEPS, 1), TPB>>>(inp, W, bias);
    rnn_kernel<<<GRID, TPB>>>(Uw, out);
}